// round 1
// baseline (speedup 1.0000x reference)
#include <cuda_runtime.h>
#include <math.h>

#define S_LEN    2048
#define DIM      3072
#define HEADS    24
#define HEAD_DIM 128

// Scratch (no cudaMalloc allowed): q, k, v post-projection
__device__ float g_q[S_LEN * DIM];
__device__ float g_k[S_LEN * DIM];
__device__ float g_v[S_LEN * DIM];

// ---------------------------------------------------------------------------
// Stage 1: QKV projection. C = x @ W + b for W in {Wq, Wk, Wv} (blockIdx.z).
// Classic 128x128x8 SGEMM, 256 threads, 8x8 register microtile.
// ---------------------------------------------------------------------------
#define BM 128
#define BN 128
#define BK 8

__global__ __launch_bounds__(256) void qkv_gemm_kernel(
    const float* __restrict__ x,
    const float* __restrict__ Wq, const float* __restrict__ bq,
    const float* __restrict__ Wk, const float* __restrict__ bk,
    const float* __restrict__ Wv, const float* __restrict__ bv)
{
    const float* W; const float* bias; float* out;
    if (blockIdx.z == 0)      { W = Wq; bias = bq; out = g_q; }
    else if (blockIdx.z == 1) { W = Wk; bias = bk; out = g_k; }
    else                      { W = Wv; bias = bv; out = g_v; }

    __shared__ float As[BK][BM];   // A transposed: As[k][m]
    __shared__ float Bs[BK][BN];

    const int tid  = threadIdx.x;
    const int row0 = blockIdx.y * BM;
    const int col0 = blockIdx.x * BN;

    const int trow = (tid / 16) * 8;
    const int tcol = (tid % 16) * 8;

    float acc[8][8];
    #pragma unroll
    for (int i = 0; i < 8; i++)
        #pragma unroll
        for (int j = 0; j < 8; j++) acc[i][j] = 0.f;

    const int arow = tid >> 1;          // 0..127
    const int acol = (tid & 1) * 4;     // 0 or 4
    const int brow = tid >> 5;          // 0..7
    const int bcol = (tid & 31) * 4;    // 0..124

    for (int k0 = 0; k0 < DIM; k0 += BK) {
        float4 av = *(const float4*)(x + (size_t)(row0 + arow) * DIM + k0 + acol);
        As[acol + 0][arow] = av.x;
        As[acol + 1][arow] = av.y;
        As[acol + 2][arow] = av.z;
        As[acol + 3][arow] = av.w;
        *(float4*)(&Bs[brow][bcol]) =
            *(const float4*)(W + (size_t)(k0 + brow) * DIM + col0 + bcol);
        __syncthreads();

        #pragma unroll
        for (int kk = 0; kk < BK; kk++) {
            float a_frag[8], b_frag[8];
            #pragma unroll
            for (int i = 0; i < 8; i++) a_frag[i] = As[kk][trow + i];
            #pragma unroll
            for (int j = 0; j < 8; j++) b_frag[j] = Bs[kk][tcol + j];
            #pragma unroll
            for (int i = 0; i < 8; i++)
                #pragma unroll
                for (int j = 0; j < 8; j++)
                    acc[i][j] += a_frag[i] * b_frag[j];
        }
        __syncthreads();
    }

    #pragma unroll
    for (int i = 0; i < 8; i++) {
        #pragma unroll
        for (int j = 0; j < 8; j += 4) {
            float4 o;
            o.x = acc[i][j + 0] + bias[col0 + tcol + j + 0];
            o.y = acc[i][j + 1] + bias[col0 + tcol + j + 1];
            o.z = acc[i][j + 2] + bias[col0 + tcol + j + 2];
            o.w = acc[i][j + 3] + bias[col0 + tcol + j + 3];
            *(float4*)(out + (size_t)(row0 + trow + i) * DIM + col0 + tcol + j) = o;
        }
    }
}

// ---------------------------------------------------------------------------
// Stage 2: per-head RMSNorm + RoPE applied in place to g_q and g_k.
// One warp per (tensor, seq, head) row of 128.
// ---------------------------------------------------------------------------
__global__ __launch_bounds__(256) void rms_rope_kernel(
    const float* __restrict__ cosb, const float* __restrict__ sinb,
    const float* __restrict__ gq, const float* __restrict__ gk)
{
    const int gw   = (blockIdx.x * blockDim.x + threadIdx.x) >> 5;
    const int lane = threadIdx.x & 31;
    const int rows = S_LEN * HEADS;
    if (gw >= 2 * rows) return;

    const int t  = (gw >= rows) ? 1 : 0;
    const int rr = t ? (gw - rows) : gw;
    const int s  = rr / HEADS;

    float* ptr = (t ? g_k : g_q) + (size_t)rr * HEAD_DIM;
    const float* g = t ? gk : gq;

    float4 vx = *(float4*)(ptr + lane * 4);
    float ss = vx.x * vx.x + vx.y * vx.y + vx.z * vx.z + vx.w * vx.w;
    #pragma unroll
    for (int o = 16; o > 0; o >>= 1) ss += __shfl_xor_sync(0xffffffffu, ss, o);
    const float rnorm = rsqrtf(ss * (1.0f / HEAD_DIM) + 1e-6f);

    float4 gg = *(const float4*)(g + lane * 4);
    vx.x *= rnorm * gg.x; vx.y *= rnorm * gg.y;
    vx.z *= rnorm * gg.z; vx.w *= rnorm * gg.w;

    float4 c  = *(const float4*)(cosb + (size_t)s * HEAD_DIM + lane * 4);
    float4 sn = *(const float4*)(sinb + (size_t)s * HEAD_DIM + lane * 4);
    // pairs: out[2i] = x[2i]*cos - x[2i+1]*sin ; out[2i+1] = x[2i+1]*cos + x[2i]*sin
    float4 o;
    o.x = vx.x * c.x - vx.y * sn.x;
    o.y = vx.y * c.y + vx.x * sn.y;
    o.z = vx.z * c.z - vx.w * sn.z;
    o.w = vx.w * c.w + vx.z * sn.w;
    *(float4*)(ptr + lane * 4) = o;
}

// ---------------------------------------------------------------------------
// Stage 3: flash attention, fp32. 64 q-rows x 64 kv-rows per tile.
// 8 warps; warp w owns q-rows [8w, 8w+8). Lane handles 2 k-cols (scores)
// and 4 output columns 4*lane..4*lane+3 (PV).
// K tile stored d-major as float4 with padded row stride 65 (conflict-free).
// P staged per-warp in smem -> only __syncwarp needed between S and PV.
// ---------------------------------------------------------------------------
#define BQ  64
#define BKV 64
#define ATTN_THREADS 256
// floats: Qs 64*128 + Kt 32*65*4 + Vs 64*128 + Ps 64*64
#define ATTN_SMEM_FLOATS (64*128 + 32*65*4 + 64*128 + 64*64)
#define ATTN_SMEM_BYTES  (ATTN_SMEM_FLOATS * 4)

__global__ __launch_bounds__(ATTN_THREADS) void attn_kernel(float* __restrict__ out)
{
    extern __shared__ float sm[];
    float* Qs = sm;                         // [64][128]
    float* Kt = Qs + 64 * 128;              // float4 grid [32][65] (d4-major)
    float* Vs = Kt + 32 * 65 * 4;           // [64][128]
    float* Ps = Vs + 64 * 128;              // [64][64]

    const int h    = blockIdx.y;
    const int q0   = blockIdx.x * BQ;
    const int tid  = threadIdx.x;
    const int warp = tid >> 5;
    const int lane = tid & 31;

    const float scale = 0.08838834764831845f;   // 1/sqrt(128)

    // Load Q tile, pre-scaled
    for (int i = tid; i < BQ * HEAD_DIM / 4; i += ATTN_THREADS) {
        const int r  = i >> 5;
        const int c4 = i & 31;
        float4 val = *(const float4*)(g_q + ((size_t)(q0 + r) * HEADS + h) * HEAD_DIM + c4 * 4);
        val.x *= scale; val.y *= scale; val.z *= scale; val.w *= scale;
        ((float4*)Qs)[i] = val;
    }

    float4 acc[8];
    float  m_i[8], l_i[8];
    #pragma unroll
    for (int r = 0; r < 8; r++) {
        acc[r] = make_float4(0.f, 0.f, 0.f, 0.f);
        m_i[r] = -INFINITY;
        l_i[r] = 0.f;
    }

    for (int kv0 = 0; kv0 < S_LEN; kv0 += BKV) {
        __syncthreads();   // previous tile's smem fully consumed
        // K tile: one float4 over d per (kk); store at [d4][kk], row stride 65
        for (int i = tid; i < BKV * HEAD_DIM / 4; i += ATTN_THREADS) {
            const int kk = i >> 5;
            const int d4 = i & 31;
            float4 val = *(const float4*)(g_k + ((size_t)(kv0 + kk) * HEADS + h) * HEAD_DIM + d4 * 4);
            ((float4*)Kt)[d4 * 65 + kk] = val;
        }
        // V tile: row-major [kk][d]
        for (int i = tid; i < BKV * HEAD_DIM / 4; i += ATTN_THREADS) {
            ((float4*)Vs)[i] =
                *(const float4*)(g_v + ((size_t)(kv0 + (i >> 5)) * HEADS + h) * HEAD_DIM + (i & 31) * 4);
        }
        __syncthreads();

        // ---- S = Q K^T (this warp's 8 rows; lane -> k cols {lane, lane+32}) ----
        float s0[8], s1[8];
        #pragma unroll
        for (int r = 0; r < 8; r++) { s0[r] = 0.f; s1[r] = 0.f; }
        const float4* Qs4 = (const float4*)Qs + (size_t)(warp * 8) * 32;
        const float4* Kt4 = (const float4*)Kt;
        #pragma unroll 4
        for (int d4 = 0; d4 < 32; d4++) {
            const float4 kb0 = Kt4[d4 * 65 + lane];
            const float4 kb1 = Kt4[d4 * 65 + lane + 32];
            #pragma unroll
            for (int r = 0; r < 8; r++) {
                const float4 qv = Qs4[r * 32 + d4];
                s0[r] += qv.x * kb0.x + qv.y * kb0.y + qv.z * kb0.z + qv.w * kb0.w;
                s1[r] += qv.x * kb1.x + qv.y * kb1.y + qv.z * kb1.z + qv.w * kb1.w;
            }
        }

        // ---- online softmax, stage P into smem (per-warp rows) ----
        #pragma unroll
        for (int r = 0; r < 8; r++) {
            float mx = fmaxf(s0[r], s1[r]);
            #pragma unroll
            for (int o = 16; o > 0; o >>= 1) mx = fmaxf(mx, __shfl_xor_sync(0xffffffffu, mx, o));
            const float m_new = fmaxf(m_i[r], mx);
            const float alpha = __expf(m_i[r] - m_new);
            const float p0 = __expf(s0[r] - m_new);
            const float p1 = __expf(s1[r] - m_new);
            float ps = p0 + p1;
            #pragma unroll
            for (int o = 16; o > 0; o >>= 1) ps += __shfl_xor_sync(0xffffffffu, ps, o);
            l_i[r] = l_i[r] * alpha + ps;
            m_i[r] = m_new;
            acc[r].x *= alpha; acc[r].y *= alpha; acc[r].z *= alpha; acc[r].w *= alpha;
            Ps[(warp * 8 + r) * 64 + lane]      = p0;
            Ps[(warp * 8 + r) * 64 + lane + 32] = p1;
        }
        __syncwarp();

        // ---- O += P V (lane owns output cols 4*lane..4*lane+3) ----
        const float4* Ps4 = (const float4*)Ps + (size_t)(warp * 8) * 16;
        const float4* Vs4 = (const float4*)Vs;
        #pragma unroll 4
        for (int kk4 = 0; kk4 < 16; kk4++) {
            float4 pv[8];
            #pragma unroll
            for (int r = 0; r < 8; r++) pv[r] = Ps4[r * 16 + kk4];
            #pragma unroll
            for (int u = 0; u < 4; u++) {
                const float4 vv = Vs4[(kk4 * 4 + u) * 32 + lane];
                #pragma unroll
                for (int r = 0; r < 8; r++) {
                    const float p = (u == 0) ? pv[r].x : (u == 1) ? pv[r].y
                                  : (u == 2) ? pv[r].z : pv[r].w;
                    acc[r].x += p * vv.x;
                    acc[r].y += p * vv.y;
                    acc[r].z += p * vv.z;
                    acc[r].w += p * vv.w;
                }
            }
        }
    }

    // epilogue: normalize and store out[b, q, h*128 + c]
    #pragma unroll
    for (int r = 0; r < 8; r++) {
        const float inv = 1.f / l_i[r];
        float4 o = acc[r];
        o.x *= inv; o.y *= inv; o.z *= inv; o.w *= inv;
        const int row = q0 + warp * 8 + r;
        *(float4*)(out + (size_t)row * DIM + h * HEAD_DIM + lane * 4) = o;
    }
}

// ---------------------------------------------------------------------------
extern "C" void kernel_launch(void* const* d_in, const int* in_sizes, int n_in,
                              void* d_out, int out_size)
{
    (void)in_sizes; (void)n_in; (void)out_size;
    const float* x  = (const float*)d_in[0];
    const float* cs = (const float*)d_in[1];
    const float* sn = (const float*)d_in[2];
    const float* Wq = (const float*)d_in[3];
    const float* bq = (const float*)d_in[4];
    const float* Wk = (const float*)d_in[5];
    const float* bk = (const float*)d_in[6];
    const float* Wv = (const float*)d_in[7];
    const float* bv = (const float*)d_in[8];
    const float* gq = (const float*)d_in[9];
    const float* gk = (const float*)d_in[10];
    float* out = (float*)d_out;

    // Stage 1: QKV projections
    dim3 gg(DIM / BN, S_LEN / BM, 3);
    qkv_gemm_kernel<<<gg, 256>>>(x, Wq, bq, Wk, bk, Wv, bv);

    // Stage 2: RMSNorm + RoPE on q, k
    const int warps  = 2 * S_LEN * HEADS;
    const int thr    = 256;
    const int blocks = (warps * 32 + thr - 1) / thr;
    rms_rope_kernel<<<blocks, thr>>>(cs, sn, gq, gk);

    // Stage 3: attention
    cudaFuncSetAttribute(attn_kernel, cudaFuncAttributeMaxDynamicSharedMemorySize,
                         ATTN_SMEM_BYTES);
    dim3 ga(S_LEN / BQ, HEADS);
    attn_kernel<<<ga, ATTN_THREADS, ATTN_SMEM_BYTES>>>(out);
}